// round 4
// baseline (speedup 1.0000x reference)
#include <cuda_runtime.h>
#include <cuda_bf16.h>
#include <cstdint>
#include <cstddef>

// ============================ problem constants ============================
#define M_TOK 4096   // B*S = 2*2048
#define D_IN  2048
#define D_FF  8192
#define R_LORA 16
#define LORA_SCALE 2.0f

#define LDK1 (D_IN + 64)   // 2112: 2048 base + 48 lora-ext + 16 zero
#define LDK2 (D_FF + 64)   // 8256

// ============================ device scratch ===============================
__device__ __align__(256) __nv_bfloat16 g_qx  [(size_t)M_TOK * LDK1];
__device__ __align__(256) __nv_bfloat16 g_qw1t[(size_t)D_FF  * LDK1];  // [N=8192][LDK1]
__device__ __align__(256) float         g_h   [(size_t)M_TOK * D_FF];
__device__ __align__(256) __nv_bfloat16 g_qh  [(size_t)M_TOK * LDK2];
__device__ __align__(256) __nv_bfloat16 g_qw2t[(size_t)D_IN  * LDK2];  // [N=2048][LDK2]
__device__ float g_xA  [M_TOK * R_LORA];
__device__ float g_hA  [M_TOK * R_LORA];
__device__ float g_part[8 * M_TOK * R_LORA];
__device__ float g_absmax[4];   // [0]=x, [1]=W_fc, [2]=W_proj, [3]=h

// ============================ PTX helpers ==================================
__device__ __forceinline__ uint32_t smem_u32(const void* p) {
    uint32_t a;
    asm("{ .reg .u64 t; cvta.to.shared.u64 t, %1; cvt.u32.u64 %0, t; }" : "=r"(a) : "l"(p));
    return a;
}
__device__ __forceinline__ void cp_async16(uint32_t saddr, const void* gptr) {
    asm volatile("cp.async.cg.shared.global [%0], [%1], 16;" :: "r"(saddr), "l"(gptr));
}
#define CP_ASYNC_COMMIT() asm volatile("cp.async.commit_group;" ::: "memory")
#define CP_ASYNC_WAIT1()  asm volatile("cp.async.wait_group 1;" ::: "memory")

__device__ __forceinline__ void ldm_x4(uint32_t* r, uint32_t addr) {
    asm volatile("ldmatrix.sync.aligned.m8n8.x4.shared.b16 {%0,%1,%2,%3}, [%4];"
                 : "=r"(r[0]), "=r"(r[1]), "=r"(r[2]), "=r"(r[3]) : "r"(addr));
}
__device__ __forceinline__ void mma16816(float* c, const uint32_t* a, uint32_t b0, uint32_t b1) {
    asm volatile("mma.sync.aligned.m16n8k16.row.col.f32.bf16.bf16.f32 "
                 "{%0,%1,%2,%3}, {%4,%5,%6,%7}, {%8,%9}, {%0,%1,%2,%3};"
                 : "+f"(c[0]), "+f"(c[1]), "+f"(c[2]), "+f"(c[3])
                 : "r"(a[0]), "r"(a[1]), "r"(a[2]), "r"(a[3]), "r"(b0), "r"(b1));
}

// ============================ small kernels ================================
__global__ void init_kernel(float* am) {
    if (threadIdx.x < 4) am[threadIdx.x] = 0.0f;
}

__global__ void absmax_kernel(const float4* __restrict__ x, int n4, float* __restrict__ out) {
    float m = 0.0f;
    for (int i = blockIdx.x * blockDim.x + threadIdx.x; i < n4; i += gridDim.x * blockDim.x) {
        float4 v = x[i];
        m = fmaxf(m, fmaxf(fmaxf(fabsf(v.x), fabsf(v.y)), fmaxf(fabsf(v.z), fabsf(v.w))));
    }
    #pragma unroll
    for (int o = 16; o; o >>= 1) m = fmaxf(m, __shfl_xor_sync(0xffffffffu, m, o));
    __shared__ float s[32];
    if ((threadIdx.x & 31) == 0) s[threadIdx.x >> 5] = m;
    __syncthreads();
    if (threadIdx.x < 32) {
        float v = (threadIdx.x < (blockDim.x >> 5)) ? s[threadIdx.x] : 0.0f;
        #pragma unroll
        for (int o = 16; o; o >>= 1) v = fmaxf(v, __shfl_xor_sync(0xffffffffu, v, o));
        if (threadIdx.x == 0) atomicMax((unsigned int*)out, __float_as_uint(v));
    }
}

struct __align__(8) bf16x4 { __nv_bfloat162 a, b; };

// strided quantize: src contiguous [M][K] fp32 -> dst [M][ldk] bf16 integers (cols 0..K-1)
__global__ void quant_kernel(const float4* __restrict__ x, bf16x4* __restrict__ q,
                             int n4, int row4, int ldk4, const float* __restrict__ am) {
    float scale = __fdiv_rn(fmaxf(am[0], 1e-8f), 127.0f);
    for (int i = blockIdx.x * blockDim.x + threadIdx.x; i < n4; i += gridDim.x * blockDim.x) {
        float4 v = x[i];
        float q0 = fminf(fmaxf(rintf(__fdiv_rn(v.x, scale)), -127.f), 127.f);
        float q1 = fminf(fmaxf(rintf(__fdiv_rn(v.y, scale)), -127.f), 127.f);
        float q2 = fminf(fmaxf(rintf(__fdiv_rn(v.z, scale)), -127.f), 127.f);
        float q3 = fminf(fmaxf(rintf(__fdiv_rn(v.w, scale)), -127.f), 127.f);
        bf16x4 o;
        o.a = __floats2bfloat162_rn(q0, q1);
        o.b = __floats2bfloat162_rn(q2, q3);
        int m = i / row4, c = i - m * row4;
        q[(size_t)m * ldk4 + c] = o;
    }
}

// Transpose + quantize: W [K,N] fp32 -> Wt [N][ldk] bf16 ints (cols 0..K-1)
__global__ void transquant_kernel(const float* __restrict__ W, __nv_bfloat16* __restrict__ Wt,
                                  int K, int N, int ldk, const float* __restrict__ am) {
    __shared__ float tile[32][33];
    float scale = __fdiv_rn(fmaxf(am[0], 1e-8f), 127.0f);
    int n0 = blockIdx.x * 32, k0 = blockIdx.y * 32;
    int tx = threadIdx.x;
    for (int i = threadIdx.y; i < 32; i += 8)
        tile[i][tx] = W[(size_t)(k0 + i) * N + n0 + tx];
    __syncthreads();
    for (int i = threadIdx.y; i < 32; i += 8) {
        float q = fminf(fmaxf(rintf(__fdiv_rn(tile[tx][i], scale)), -127.f), 127.f);
        Wt[(size_t)(n0 + i) * ldk + k0 + tx] = __float2bfloat16_rn(q);
    }
}

// LoRA ext columns, A side: cols kb+r = a_hi, kb+16+r = a_hi, kb+32+r = a_lo, kb+48+r = 0
__global__ void extA_kernel(const float* __restrict__ xa, __nv_bfloat16* __restrict__ qA,
                            int ldk, int kb, const float* __restrict__ amA,
                            const float* __restrict__ amB) {
    int i = blockIdx.x * blockDim.x + threadIdx.x;
    if (i >= M_TOK * R_LORA) return;
    int m = i >> 4, r = i & 15;
    float cs = __fdiv_rn(fmaxf(amA[0], 1e-8f), 127.0f) * __fdiv_rn(fmaxf(amB[0], 1e-8f), 127.0f);
    float a = xa[i] * (LORA_SCALE / cs);
    __nv_bfloat16 hi = __float2bfloat16_rn(a);
    __nv_bfloat16 lo = __float2bfloat16_rn(a - __bfloat162float(hi));
    __nv_bfloat16* row = qA + (size_t)m * ldk + kb;
    row[r] = hi; row[16 + r] = hi; row[32 + r] = lo; row[48 + r] = __float2bfloat16_rn(0.f);
}

// LoRA ext columns, B side (Bmat [16][N]): cols kb+r = b_hi, kb+16+r = b_lo, kb+32+r = b_hi, 48..63 = 0
__global__ void extB_kernel(const float* __restrict__ Bmat, __nv_bfloat16* __restrict__ qB,
                            int n_total, int ldk, int kb) {
    int i = blockIdx.x * blockDim.x + threadIdx.x;
    if (i >= n_total * R_LORA) return;
    int n = i >> 4, r = i & 15;
    float b = Bmat[(size_t)r * n_total + n];
    __nv_bfloat16 hi = __float2bfloat16_rn(b);
    __nv_bfloat16 lo = __float2bfloat16_rn(b - __bfloat162float(hi));
    __nv_bfloat16* row = qB + (size_t)n * ldk + kb;
    row[r] = hi; row[16 + r] = lo; row[32 + r] = hi; row[48 + r] = __float2bfloat16_rn(0.f);
}

// Skinny GEMM partials: part[sp][m][16] = X[m, seg_sp] @ A[seg_sp, 16]
__global__ void rowA_kernel(const float* __restrict__ X, const float* __restrict__ A,
                            float* __restrict__ part, int K, int nsplit) {
    int t = threadIdx.x;
    int m = blockIdx.x * 64 + (t >> 1);
    int rh = t & 1;
    int kseg = K / nsplit;
    int kbeg = blockIdx.y * kseg;
    float acc[8];
    #pragma unroll
    for (int j = 0; j < 8; j++) acc[j] = 0.0f;
    const float4* x4 = (const float4*)(X + (size_t)m * K + kbeg);
    for (int d4 = 0; d4 < kseg / 4; d4++) {
        float4 xv = x4[d4];
        float xs[4] = {xv.x, xv.y, xv.z, xv.w};
        int d = kbeg + d4 * 4;
        #pragma unroll
        for (int j = 0; j < 4; j++) {
            const float4* ap = (const float4*)(A + (size_t)(d + j) * 16 + rh * 8);
            float4 a0 = ap[0], a1 = ap[1];
            acc[0] += xs[j] * a0.x;  acc[1] += xs[j] * a0.y;
            acc[2] += xs[j] * a0.z;  acc[3] += xs[j] * a0.w;
            acc[4] += xs[j] * a1.x;  acc[5] += xs[j] * a1.y;
            acc[6] += xs[j] * a1.z;  acc[7] += xs[j] * a1.w;
        }
    }
    float* o = part + ((size_t)blockIdx.y * M_TOK + m) * 16 + rh * 8;
    #pragma unroll
    for (int j = 0; j < 8; j++) o[j] = acc[j];
}

__global__ void rowA_reduce(const float* __restrict__ part, float* __restrict__ out, int nsplit) {
    int i = blockIdx.x * blockDim.x + threadIdx.x;
    if (i < M_TOK * 16) {
        float s = 0.0f;
        for (int sp = 0; sp < nsplit; sp++) s += part[(size_t)sp * (M_TOK * 16) + i];
        out[i] = s;
    }
}

// ============================ mma.sync GEMM ================================
// CTA 128x128, k-chunk 64, 3-stage cp.async pipeline, 8 warps (2m x 4n), warp 64x32.
// smem tile: 128 rows x 128B, chunk swizzle ch ^= (row & 7).
static constexpr int STAGE_BYTES = 32768;              // A 16KB + B 16KB
static constexpr int SMEM_GEMM   = 3 * STAGE_BYTES + 512;

__device__ __forceinline__ void load_tile(uint32_t sbase, const __nv_bfloat16* __restrict__ src,
                                          int row0, int k0, int ldk) {
    int tid = threadIdx.x;
    #pragma unroll
    for (int i = 0; i < 4; i++) {
        int idx = i * 256 + tid;          // 0..1023 16B chunks
        int r   = idx >> 3;               // row 0..127
        int ch  = idx & 7;                // chunk 0..7
        uint32_t dst = sbase + r * 128 + ((ch ^ (r & 7)) << 4);
        cp_async16(dst, src + (size_t)(row0 + r) * ldk + k0 + ch * 8);
    }
}

template <int KPAD, int NCOLS, bool LAYER1>
__global__ void __launch_bounds__(256)
gemm_mma(const __nv_bfloat16* __restrict__ Aq, const __nv_bfloat16* __restrict__ Bq,
         const float* __restrict__ bias, const float* __restrict__ amA,
         const float* __restrict__ amB, float* __restrict__ Out, float* __restrict__ amOut) {
    extern __shared__ char smem[];
    uint32_t sb = smem_u32(smem);
    int tid = threadIdx.x, wid = tid >> 5, lane = tid & 31;
    constexpr int NT = NCOLS / 128;
    int mt = blockIdx.x / NT, nt = blockIdx.x % NT;
    int m0 = mt * 128, n0 = nt * 128;
    int m0w = (wid >> 2) * 64;     // 0 / 64
    int n0w = (wid & 3) * 32;      // 0,32,64,96

    float* bs = (float*)(smem + 3 * STAGE_BYTES);
    if (tid < 128) bs[tid] = bias[n0 + tid];

    constexpr int NKC = KPAD / 64;
    load_tile(sb, Aq, m0, 0, KPAD);
    load_tile(sb + 16384, Bq, n0, 0, KPAD);
    CP_ASYNC_COMMIT();
    load_tile(sb + STAGE_BYTES, Aq, m0, 64, KPAD);
    load_tile(sb + STAGE_BYTES + 16384, Bq, n0, 64, KPAD);
    CP_ASYNC_COMMIT();

    float acc[4][4][4];
    #pragma unroll
    for (int a = 0; a < 4; a++)
        #pragma unroll
        for (int b = 0; b < 4; b++)
            #pragma unroll
            for (int c = 0; c < 4; c++) acc[a][b][c] = 0.0f;

    // ldmatrix per-lane addressing
    int rA = lane & 15, selA = lane >> 4;                 // A frag rows/k-half
    int rB = ((lane >> 4) << 3) | (lane & 7);             // B frag rows (n)
    int selB = (lane >> 3) & 1;                           // B k-half
    uint32_t rowA = (uint32_t)(m0w + rA) * 128;
    uint32_t rowB = (uint32_t)(n0w + rB) * 128;
    uint32_t swA = (uint32_t)(rA & 7), swB = (uint32_t)(rB & 7);

    for (int kc = 0; kc < NKC; kc++) {
        CP_ASYNC_WAIT1();
        __syncthreads();
        if (kc + 2 < NKC) {
            int st = (kc + 2) % 3;
            load_tile(sb + st * STAGE_BYTES, Aq, m0, (kc + 2) * 64, KPAD);
            load_tile(sb + st * STAGE_BYTES + 16384, Bq, n0, (kc + 2) * 64, KPAD);
        }
        CP_ASYNC_COMMIT();
        uint32_t bA = sb + (kc % 3) * STAGE_BYTES;
        uint32_t bB = bA + 16384;
        #pragma unroll
        for (int kq = 0; kq < 4; kq++) {
            uint32_t afr[4][4], bfr[2][4];
            uint32_t chA = (((uint32_t)(2 * kq + selA) ^ swA) << 4);
            uint32_t chB = (((uint32_t)(2 * kq + selB) ^ swB) << 4);
            #pragma unroll
            for (int im = 0; im < 4; im++)
                ldm_x4(afr[im], bA + rowA + im * 16 * 128 + chA);
            #pragma unroll
            for (int p = 0; p < 2; p++)
                ldm_x4(bfr[p], bB + rowB + p * 16 * 128 + chB);
            #pragma unroll
            for (int im = 0; im < 4; im++)
                #pragma unroll
                for (int in = 0; in < 4; in++)
                    mma16816(acc[im][in], afr[im], bfr[in >> 1][(in & 1) * 2],
                             bfr[in >> 1][(in & 1) * 2 + 1]);
        }
    }
    __syncthreads();

    float cs = __fdiv_rn(fmaxf(amA[0], 1e-8f), 127.0f) *
               __fdiv_rn(fmaxf(amB[0], 1e-8f), 127.0f);
    float lmax = 0.0f;
    #pragma unroll
    for (int im = 0; im < 4; im++) {
        int mrow = m0 + m0w + im * 16 + (lane >> 2);
        #pragma unroll
        for (int in = 0; in < 4; in++) {
            int ncol = n0w + in * 8 + 2 * (lane & 3);
            float b0 = bs[ncol], b1 = bs[ncol + 1];
            float v0 = acc[im][in][0] * cs + b0;
            float v1 = acc[im][in][1] * cs + b1;
            float v2 = acc[im][in][2] * cs + b0;
            float v3 = acc[im][in][3] * cs + b1;
            if (LAYER1) {
                v0 = 0.5f * v0 * (1.0f + erff(v0 * 0.70710678118654752f));
                v1 = 0.5f * v1 * (1.0f + erff(v1 * 0.70710678118654752f));
                v2 = 0.5f * v2 * (1.0f + erff(v2 * 0.70710678118654752f));
                v3 = 0.5f * v3 * (1.0f + erff(v3 * 0.70710678118654752f));
                lmax = fmaxf(lmax, fmaxf(fmaxf(fabsf(v0), fabsf(v1)),
                                         fmaxf(fabsf(v2), fabsf(v3))));
            }
            float2 w0 = {v0, v1}, w1 = {v2, v3};
            *(float2*)&Out[(size_t)mrow * NCOLS + n0 + ncol] = w0;
            *(float2*)&Out[(size_t)(mrow + 8) * NCOLS + n0 + ncol] = w1;
        }
    }
    if (LAYER1) {
        #pragma unroll
        for (int o = 16; o; o >>= 1) lmax = fmaxf(lmax, __shfl_xor_sync(0xffffffffu, lmax, o));
        if (lane == 0) atomicMax((unsigned int*)amOut, __float_as_uint(lmax));
    }
}

// ============================ launch ======================================
extern "C" void kernel_launch(void* const* d_in, const int* in_sizes, int n_in,
                              void* d_out, int out_size) {
    (void)in_sizes; (void)n_in; (void)out_size;
    const float* x      = (const float*)d_in[0];
    const float* W_fc   = (const float*)d_in[1];
    const float* b_fc   = (const float*)d_in[2];
    const float* A_fc   = (const float*)d_in[3];
    const float* B_fc   = (const float*)d_in[4];
    const float* W_proj = (const float*)d_in[5];
    const float* b_proj = (const float*)d_in[6];
    const float* A_proj = (const float*)d_in[7];
    const float* B_proj = (const float*)d_in[8];
    float* out = (float*)d_out;

    void* p;
    cudaGetSymbolAddress(&p, g_qx);     __nv_bfloat16* qx   = (__nv_bfloat16*)p;
    cudaGetSymbolAddress(&p, g_qw1t);   __nv_bfloat16* qw1t = (__nv_bfloat16*)p;
    cudaGetSymbolAddress(&p, g_h);      float* h            = (float*)p;
    cudaGetSymbolAddress(&p, g_qh);     __nv_bfloat16* qh   = (__nv_bfloat16*)p;
    cudaGetSymbolAddress(&p, g_qw2t);   __nv_bfloat16* qw2t = (__nv_bfloat16*)p;
    cudaGetSymbolAddress(&p, g_xA);     float* xA           = (float*)p;
    cudaGetSymbolAddress(&p, g_hA);     float* hA           = (float*)p;
    cudaGetSymbolAddress(&p, g_part);   float* part         = (float*)p;
    cudaGetSymbolAddress(&p, g_absmax); float* am           = (float*)p;

    cudaFuncSetAttribute(gemm_mma<LDK1, D_FF, true>,
                         cudaFuncAttributeMaxDynamicSharedMemorySize, SMEM_GEMM);
    cudaFuncSetAttribute(gemm_mma<LDK2, D_IN, false>,
                         cudaFuncAttributeMaxDynamicSharedMemorySize, SMEM_GEMM);

    const size_t nX = (size_t)M_TOK * D_IN;
    const size_t nW = (size_t)D_IN * D_FF;
    const size_t nH = (size_t)M_TOK * D_FF;

    // 1) reset absmax scratch (graph-replay determinism)
    init_kernel<<<1, 32>>>(am);
    // 2) per-tensor absmax
    absmax_kernel<<<512, 256>>>((const float4*)x,      (int)(nX / 4), am + 0);
    absmax_kernel<<<512, 256>>>((const float4*)W_fc,   (int)(nW / 4), am + 1);
    absmax_kernel<<<512, 256>>>((const float4*)W_proj, (int)(nW / 4), am + 2);
    // 3) quantize (strided dst) + transpose-quantize weights
    quant_kernel<<<512, 256>>>((const float4*)x, (bf16x4*)qx, (int)(nX / 4),
                               D_IN / 4, LDK1 / 4, am + 0);
    transquant_kernel<<<dim3(D_FF / 32, D_IN / 32), dim3(32, 8)>>>(W_fc,   qw1t, D_IN, D_FF, LDK1, am + 1);
    transquant_kernel<<<dim3(D_IN / 32, D_FF / 32), dim3(32, 8)>>>(W_proj, qw2t, D_FF, D_IN, LDK2, am + 2);
    // 4) LoRA: xA = x @ A_fc, then ext columns for both operands
    rowA_kernel<<<dim3(M_TOK / 64, 2), 128>>>(x, A_fc, part, D_IN, 2);
    rowA_reduce<<<(M_TOK * 16 + 255) / 256, 256>>>(part, xA, 2);
    extA_kernel<<<(M_TOK * 16 + 255) / 256, 256>>>(xA, qx, LDK1, D_IN, am + 0, am + 1);
    extB_kernel<<<(D_FF * 16 + 255) / 256, 256>>>(B_fc, qw1t, D_FF, LDK1, D_IN);
    // 5) GEMM1 + bias + GELU -> h (fused absmax)
    gemm_mma<LDK1, D_FF, true><<<(M_TOK / 128) * (D_FF / 128), 256, SMEM_GEMM>>>(
        qx, qw1t, b_fc, am + 0, am + 1, h, am + 3);
    // 6) hA = h @ A_proj; quantize h; ext columns
    rowA_kernel<<<dim3(M_TOK / 64, 8), 128>>>(h, A_proj, part, D_FF, 8);
    rowA_reduce<<<(M_TOK * 16 + 255) / 256, 256>>>(part, hA, 8);
    quant_kernel<<<1024, 256>>>((const float4*)h, (bf16x4*)qh, (int)(nH / 4),
                                D_FF / 4, LDK2 / 4, am + 3);
    extA_kernel<<<(M_TOK * 16 + 255) / 256, 256>>>(hA, qh, LDK2, D_FF, am + 3, am + 2);
    extB_kernel<<<(D_IN * 16 + 255) / 256, 256>>>(B_proj, qw2t, D_IN, LDK2, D_FF);
    // 7) GEMM2 + bias -> out
    gemm_mma<LDK2, D_IN, false><<<(M_TOK / 128) * (D_IN / 128), 256, SMEM_GEMM>>>(
        qh, qw2t, b_proj, am + 3, am + 2, out, nullptr);
}

// round 5
// speedup vs baseline: 1.3864x; 1.3864x over previous
#include <cuda_runtime.h>
#include <cuda_bf16.h>
#include <cstdint>
#include <cstddef>

// ============================ problem constants ============================
#define M_TOK 4096
#define D_IN  2048
#define D_FF  8192
#define R_LORA 16
#define LORA_SCALE 2.0f

// ============================ device scratch ===============================
__device__ __align__(256) int8_t g_qx  [(size_t)M_TOK * D_IN];
__device__ __align__(256) int8_t g_qw1t[(size_t)D_FF  * D_IN];   // [N][K]
__device__ __align__(256) float  g_h   [(size_t)M_TOK * D_FF];
__device__ __align__(256) int8_t g_qh  [(size_t)M_TOK * D_FF];
__device__ __align__(256) int8_t g_qw2t[(size_t)D_IN  * D_FF];   // [N][K]
__device__ __align__(256) __nv_bfloat16 g_qxe [(size_t)M_TOK * 64];
__device__ __align__(256) __nv_bfloat16 g_qw1e[(size_t)D_FF  * 64];
__device__ __align__(256) __nv_bfloat16 g_qhe [(size_t)M_TOK * 64];
__device__ __align__(256) __nv_bfloat16 g_qw2e[(size_t)D_IN  * 64];
__device__ float g_part[16 * M_TOK * R_LORA];
__device__ float g_absmax[4];   // [0]=x, [1]=W_fc, [2]=W_proj, [3]=h

// ============================ PTX helpers ==================================
__device__ __forceinline__ uint32_t smem_u32(const void* p) {
    uint32_t a;
    asm("{ .reg .u64 t; cvta.to.shared.u64 t, %1; cvt.u32.u64 %0, t; }" : "=r"(a) : "l"(p));
    return a;
}
__device__ __forceinline__ void cp_async16(uint32_t saddr, const void* gptr) {
    asm volatile("cp.async.cg.shared.global [%0], [%1], 16;" :: "r"(saddr), "l"(gptr));
}
#define CP_ASYNC_COMMIT() asm volatile("cp.async.commit_group;" ::: "memory")
#define CP_ASYNC_WAIT1()  asm volatile("cp.async.wait_group 1;" ::: "memory")

__device__ __forceinline__ void ldm_x4(uint32_t* r, uint32_t addr) {
    asm volatile("ldmatrix.sync.aligned.m8n8.x4.shared.b16 {%0,%1,%2,%3}, [%4];"
                 : "=r"(r[0]), "=r"(r[1]), "=r"(r[2]), "=r"(r[3]) : "r"(addr));
}
__device__ __forceinline__ void mma16816(float* c, const uint32_t* a, uint32_t b0, uint32_t b1) {
    asm volatile("mma.sync.aligned.m16n8k16.row.col.f32.bf16.bf16.f32 "
                 "{%0,%1,%2,%3}, {%4,%5,%6,%7}, {%8,%9}, {%0,%1,%2,%3};"
                 : "+f"(c[0]), "+f"(c[1]), "+f"(c[2]), "+f"(c[3])
                 : "r"(a[0]), "r"(a[1]), "r"(a[2]), "r"(a[3]), "r"(b0), "r"(b1));
}
__device__ __forceinline__ void mma16832(int* c, const uint32_t* a, uint32_t b0, uint32_t b1) {
    asm volatile("mma.sync.aligned.m16n8k32.row.col.s32.s8.s8.s32 "
                 "{%0,%1,%2,%3}, {%4,%5,%6,%7}, {%8,%9}, {%0,%1,%2,%3};"
                 : "+r"(c[0]), "+r"(c[1]), "+r"(c[2]), "+r"(c[3])
                 : "r"(a[0]), "r"(a[1]), "r"(a[2]), "r"(a[3]), "r"(b0), "r"(b1));
}

// ============================ small kernels ================================
__global__ void init_kernel(float* am) {
    if (threadIdx.x < 4) am[threadIdx.x] = 0.0f;
}

// one kernel, three tensors in parallel
__global__ void absmax3_kernel(const float4* __restrict__ x, const float4* __restrict__ w1,
                               const float4* __restrict__ w2, float* __restrict__ am) {
    const int NX4 = M_TOK * D_IN / 4, NW4 = D_IN * D_FF / 4;
    const float4* src; int n4, nb, bl; float* out;
    int b = blockIdx.x;
    if (b < 512)       { src = x;  n4 = NX4; out = am;     bl = b;        nb = 512;  }
    else if (b < 1536) { src = w1; n4 = NW4; out = am + 1; bl = b - 512;  nb = 1024; }
    else               { src = w2; n4 = NW4; out = am + 2; bl = b - 1536; nb = 1024; }
    float m = 0.0f;
    for (int i = bl * blockDim.x + threadIdx.x; i < n4; i += nb * blockDim.x) {
        float4 v = src[i];
        m = fmaxf(m, fmaxf(fmaxf(fabsf(v.x), fabsf(v.y)), fmaxf(fabsf(v.z), fabsf(v.w))));
    }
    #pragma unroll
    for (int o = 16; o; o >>= 1) m = fmaxf(m, __shfl_xor_sync(0xffffffffu, m, o));
    __shared__ float s[8];
    if ((threadIdx.x & 31) == 0) s[threadIdx.x >> 5] = m;
    __syncthreads();
    if (threadIdx.x < 32) {
        float v = (threadIdx.x < 8) ? s[threadIdx.x] : 0.0f;
        #pragma unroll
        for (int o = 4; o; o >>= 1) v = fmaxf(v, __shfl_xor_sync(0xffffffffu, v, o));
        if (threadIdx.x == 0) atomicMax((unsigned int*)out, __float_as_uint(v));
    }
}

__device__ __forceinline__ uint32_t pack4(float4 v, float inv) {
    int q0 = (int)fminf(fmaxf(rintf(v.x * inv), -127.f), 127.f);
    int q1 = (int)fminf(fmaxf(rintf(v.y * inv), -127.f), 127.f);
    int q2 = (int)fminf(fmaxf(rintf(v.z * inv), -127.f), 127.f);
    int q3 = (int)fminf(fmaxf(rintf(v.w * inv), -127.f), 127.f);
    return (uint32_t)(q0 & 255) | ((uint32_t)(q1 & 255) << 8) |
           ((uint32_t)(q2 & 255) << 16) | ((uint32_t)(q3 & 255) << 24);
}

// Fused: LoRA-A partials (X @ A16 per k-segment) + int8 quantization of X.
// grid (M/64, K/1024), 128 threads. part split index sp = by*2 + (t&1).
__global__ void __launch_bounds__(128)
quantRowA_kernel(const float* __restrict__ X, const float* __restrict__ A16,
                 int8_t* __restrict__ Q, float* __restrict__ part,
                 int K, const float* __restrict__ am) {
    int t = threadIdx.x;
    int m = blockIdx.x * 64 + (t >> 1);
    int rh = t & 1;
    int kbeg = blockIdx.y * 1024 + rh * 512;
    float acc[16];
    #pragma unroll
    for (int j = 0; j < 16; j++) acc[j] = 0.0f;
    const float4* x4 = (const float4*)(X + (size_t)m * K + kbeg);
    for (int d4 = 0; d4 < 128; d4++) {
        float4 v = x4[d4];
        float xs[4] = {v.x, v.y, v.z, v.w};
        int d = kbeg + d4 * 4;
        #pragma unroll
        for (int j = 0; j < 4; j++) {
            const float4* ap = (const float4*)(A16 + (size_t)(d + j) * 16);
            float4 a0 = ap[0], a1 = ap[1], a2 = ap[2], a3 = ap[3];
            acc[0]  += xs[j] * a0.x; acc[1]  += xs[j] * a0.y;
            acc[2]  += xs[j] * a0.z; acc[3]  += xs[j] * a0.w;
            acc[4]  += xs[j] * a1.x; acc[5]  += xs[j] * a1.y;
            acc[6]  += xs[j] * a1.z; acc[7]  += xs[j] * a1.w;
            acc[8]  += xs[j] * a2.x; acc[9]  += xs[j] * a2.y;
            acc[10] += xs[j] * a2.z; acc[11] += xs[j] * a2.w;
            acc[12] += xs[j] * a3.x; acc[13] += xs[j] * a3.y;
            acc[14] += xs[j] * a3.z; acc[15] += xs[j] * a3.w;
        }
    }
    int sp = blockIdx.y * 2 + rh;
    float* o = part + ((size_t)sp * M_TOK + m) * 16;
    #pragma unroll
    for (int j = 0; j < 16; j++) o[j] = acc[j];
    // phase 2: int8 quantize this block's 64x1024 region (re-read, L2-hot)
    float inv = __fdiv_rn(127.0f, fmaxf(am[0], 1e-8f));
    for (int i = t; i < 4096; i += 128) {
        int row = blockIdx.x * 64 + (i >> 6);
        int col = blockIdx.y * 1024 + (i & 63) * 16;
        const float4* src = (const float4*)(X + (size_t)row * K + col);
        float4 v0 = src[0], v1 = src[1], v2 = src[2], v3 = src[3];
        uint4 w = { pack4(v0, inv), pack4(v1, inv), pack4(v2, inv), pack4(v3, inv) };
        *(uint4*)(Q + (size_t)row * K + col) = w;
    }
}

// Transpose + quantize both weight matrices: W [K,N] fp32 -> Wt [N][K] int8
__global__ void tqBoth_kernel(const float* __restrict__ W1, int8_t* __restrict__ Wt1,
                              const float* __restrict__ W2, int8_t* __restrict__ Wt2,
                              const float* __restrict__ am) {
    __shared__ float tile[32][33];
    const float* W; int8_t* Wt; int K, N; float inv;
    int bid = blockIdx.x, bx, by;
    if (bid < 16384) { W = W1; Wt = Wt1; K = D_IN; N = D_FF;
                       bx = bid % 256; by = bid / 256;
                       inv = __fdiv_rn(127.0f, fmaxf(am[1], 1e-8f)); }
    else             { int i = bid - 16384; W = W2; Wt = Wt2; K = D_FF; N = D_IN;
                       bx = i % 64; by = i / 64;
                       inv = __fdiv_rn(127.0f, fmaxf(am[2], 1e-8f)); }
    int n0 = bx * 32, k0 = by * 32;
    int tx = threadIdx.x;
    for (int i = threadIdx.y; i < 32; i += 8)
        tile[i][tx] = W[(size_t)(k0 + i) * N + n0 + tx];
    __syncthreads();
    for (int i = threadIdx.y; i < 32; i += 8) {
        float q = fminf(fmaxf(rintf(tile[tx][i] * inv), -127.f), 127.f);
        Wt[(size_t)(n0 + i) * K + k0 + tx] = (int8_t)(int)q;
    }
}

__device__ __forceinline__ void write_extA(__nv_bfloat16* row, int r, float a) {
    __nv_bfloat16 hi = __float2bfloat16_rn(a);
    __nv_bfloat16 lo = __float2bfloat16_rn(a - __bfloat162float(hi));
    row[r] = hi; row[16 + r] = hi; row[32 + r] = lo; row[48 + r] = __float2bfloat16_rn(0.f);
}
__device__ __forceinline__ void write_extB(__nv_bfloat16* row, int r, float b) {
    __nv_bfloat16 hi = __float2bfloat16_rn(b);
    __nv_bfloat16 lo = __float2bfloat16_rn(b - __bfloat162float(hi));
    row[r] = hi; row[16 + r] = lo; row[32 + r] = hi; row[48 + r] = __float2bfloat16_rn(0.f);
}

// reduce part(4 splits) -> qxe ; extB for both layers. flat grid 896 x 256
__global__ void ext_all_kernel(const float* __restrict__ part,
                               const float* __restrict__ B_fc, const float* __restrict__ B_proj,
                               __nv_bfloat16* __restrict__ qxe,
                               __nv_bfloat16* __restrict__ qw1e,
                               __nv_bfloat16* __restrict__ qw2e) {
    int gid = blockIdx.x * 256 + threadIdx.x;
    if (gid < M_TOK * 16) {
        int m = gid >> 4, r = gid & 15;
        float s = 0.0f;
        for (int sp = 0; sp < 4; sp++) s += part[((size_t)sp * M_TOK + m) * 16 + r];
        write_extA(qxe + (size_t)m * 64, r, s * LORA_SCALE);
    } else if (gid < M_TOK * 16 + D_FF * 16) {
        int i = gid - M_TOK * 16; int n = i >> 4, r = i & 15;
        write_extB(qw1e + (size_t)n * 64, r, B_fc[(size_t)r * D_FF + n]);
    } else if (gid < M_TOK * 16 + D_FF * 16 + D_IN * 16) {
        int i = gid - M_TOK * 16 - D_FF * 16; int n = i >> 4, r = i & 15;
        write_extB(qw2e + (size_t)n * 64, r, B_proj[(size_t)r * D_IN + n]);
    }
}

// reduce part(16 splits) -> qhe
__global__ void reduceExtA_kernel(const float* __restrict__ part, __nv_bfloat16* __restrict__ qhe) {
    int gid = blockIdx.x * 256 + threadIdx.x;
    if (gid < M_TOK * 16) {
        int m = gid >> 4, r = gid & 15;
        float s = 0.0f;
        for (int sp = 0; sp < 16; sp++) s += part[((size_t)sp * M_TOK + m) * 16 + r];
        write_extA(qhe + (size_t)m * 64, r, s * LORA_SCALE);
    }
}

// ============================ int8 mma GEMM ================================
// CTA 128x128, k-chunk 128(int8 bytes), 3-stage cp.async pipeline, 8 warps (2m x 4n),
// warp 64x32. smem rows 128B, chunk swizzle ch ^= (row & 7). LoRA ext: 64-col bf16
// side tiles, 3 k16 bf16 mma steps, fp32 accumulated.
static constexpr int STAGE_BYTES = 32768;              // A 16KB + B 16KB
static constexpr int EXT_OFF     = 3 * STAGE_BYTES;    // extA 16KB + extB 16KB
static constexpr int BIAS_OFF    = EXT_OFF + 32768;
static constexpr int SMEM_GEMM   = BIAS_OFF + 640;

__device__ __forceinline__ void load_tile8(uint32_t sbase, const int8_t* __restrict__ src,
                                           int row0, int k0, int ldk) {
    int tid = threadIdx.x;
    #pragma unroll
    for (int i = 0; i < 4; i++) {
        int idx = i * 256 + tid;
        int r   = idx >> 3;
        int ch  = idx & 7;
        uint32_t dst = sbase + r * 128 + ((ch ^ (r & 7)) << 4);
        cp_async16(dst, src + (size_t)(row0 + r) * ldk + k0 + ch * 16);
    }
}
__device__ __forceinline__ void load_tile16(uint32_t sbase, const __nv_bfloat16* __restrict__ src,
                                            int row0, int ldk) {
    int tid = threadIdx.x;
    #pragma unroll
    for (int i = 0; i < 4; i++) {
        int idx = i * 256 + tid;
        int r   = idx >> 3;
        int ch  = idx & 7;
        uint32_t dst = sbase + r * 128 + ((ch ^ (r & 7)) << 4);
        cp_async16(dst, src + (size_t)(row0 + r) * ldk + ch * 8);
    }
}

template <int KTOT, int NCOLS, bool LAYER1>
__global__ void __launch_bounds__(256, 1)
gemm_i8(const int8_t* __restrict__ Aq, const int8_t* __restrict__ Bq,
        const __nv_bfloat16* __restrict__ Ae, const __nv_bfloat16* __restrict__ Be,
        const float* __restrict__ bias, const float* __restrict__ amA,
        const float* __restrict__ amB, float* __restrict__ Out, float* __restrict__ amOut) {
    extern __shared__ char smem[];
    uint32_t sb = smem_u32(smem);
    int tid = threadIdx.x, wid = tid >> 5, lane = tid & 31;
    constexpr int NT = NCOLS / 128;
    int mt = blockIdx.x / NT, nt = blockIdx.x % NT;
    int m0 = mt * 128, n0 = nt * 128;
    int m0w = (wid >> 2) * 64;
    int n0w = (wid & 3) * 32;

    float* bs = (float*)(smem + BIAS_OFF);
    if (tid < 128) bs[tid] = bias[n0 + tid];

    // ext tiles (group 0), then stages 0,1
    load_tile16(sb + EXT_OFF, Ae, m0, 64);
    load_tile16(sb + EXT_OFF + 16384, Be, n0, 64);
    CP_ASYNC_COMMIT();
    constexpr int NKC = KTOT / 128;
    load_tile8(sb, Aq, m0, 0, KTOT);
    load_tile8(sb + 16384, Bq, n0, 0, KTOT);
    CP_ASYNC_COMMIT();
    load_tile8(sb + STAGE_BYTES, Aq, m0, 128, KTOT);
    load_tile8(sb + STAGE_BYTES + 16384, Bq, n0, 128, KTOT);
    CP_ASYNC_COMMIT();

    int iacc[4][4][4];
    #pragma unroll
    for (int a = 0; a < 4; a++)
        #pragma unroll
        for (int b = 0; b < 4; b++)
            #pragma unroll
            for (int c = 0; c < 4; c++) iacc[a][b][c] = 0;

    int rA = lane & 15, selA = lane >> 4;
    int rB = ((lane >> 4) << 3) | (lane & 7);
    int selB = (lane >> 3) & 1;
    uint32_t rowA = (uint32_t)(m0w + rA) * 128;
    uint32_t rowB = (uint32_t)(n0w + rB) * 128;
    uint32_t swA = (uint32_t)(rA & 7), swB = (uint32_t)(rB & 7);

    for (int kc = 0; kc < NKC; kc++) {
        CP_ASYNC_WAIT1();
        __syncthreads();
        if (kc + 2 < NKC) {
            int st = (kc + 2) % 3;
            load_tile8(sb + st * STAGE_BYTES, Aq, m0, (kc + 2) * 128, KTOT);
            load_tile8(sb + st * STAGE_BYTES + 16384, Bq, n0, (kc + 2) * 128, KTOT);
        }
        CP_ASYNC_COMMIT();
        uint32_t bA = sb + (kc % 3) * STAGE_BYTES;
        uint32_t bB = bA + 16384;
        #pragma unroll
        for (int kq = 0; kq < 4; kq++) {
            uint32_t afr[4][4], bfr[2][4];
            uint32_t chA = (((uint32_t)(2 * kq + selA) ^ swA) << 4);
            uint32_t chB = (((uint32_t)(2 * kq + selB) ^ swB) << 4);
            #pragma unroll
            for (int im = 0; im < 4; im++)
                ldm_x4(afr[im], bA + rowA + im * 16 * 128 + chA);
            #pragma unroll
            for (int p = 0; p < 2; p++)
                ldm_x4(bfr[p], bB + rowB + p * 16 * 128 + chB);
            #pragma unroll
            for (int im = 0; im < 4; im++)
                #pragma unroll
                for (int in = 0; in < 4; in++)
                    mma16832(iacc[im][in], afr[im], bfr[in >> 1][(in & 1) * 2],
                             bfr[in >> 1][(in & 1) * 2 + 1]);
        }
    }

    // LoRA ext pass: bf16, 3 k16 steps over the 64-col tiles (cols 48-63 are zero)
    float facc[4][4][4];
    #pragma unroll
    for (int a = 0; a < 4; a++)
        #pragma unroll
        for (int b = 0; b < 4; b++)
            #pragma unroll
            for (int c = 0; c < 4; c++) facc[a][b][c] = 0.0f;
    {
        uint32_t eA = sb + EXT_OFF, eB = sb + EXT_OFF + 16384;
        #pragma unroll
        for (int kq = 0; kq < 3; kq++) {
            uint32_t afr[4][4], bfr[2][4];
            uint32_t chA = (((uint32_t)(2 * kq + selA) ^ swA) << 4);
            uint32_t chB = (((uint32_t)(2 * kq + selB) ^ swB) << 4);
            #pragma unroll
            for (int im = 0; im < 4; im++)
                ldm_x4(afr[im], eA + rowA + im * 16 * 128 + chA);
            #pragma unroll
            for (int p = 0; p < 2; p++)
                ldm_x4(bfr[p], eB + rowB + p * 16 * 128 + chB);
            #pragma unroll
            for (int im = 0; im < 4; im++)
                #pragma unroll
                for (int in = 0; in < 4; in++)
                    mma16816(facc[im][in], afr[im], bfr[in >> 1][(in & 1) * 2],
                             bfr[in >> 1][(in & 1) * 2 + 1]);
        }
    }

    float cs = __fdiv_rn(fmaxf(amA[0], 1e-8f), 127.0f) *
               __fdiv_rn(fmaxf(amB[0], 1e-8f), 127.0f);
    float lmax = 0.0f;
    #pragma unroll
    for (int im = 0; im < 4; im++) {
        int mrow = m0 + m0w + im * 16 + (lane >> 2);
        #pragma unroll
        for (int in = 0; in < 4; in++) {
            int ncol = n0w + in * 8 + 2 * (lane & 3);
            float b0 = bs[ncol], b1 = bs[ncol + 1];
            float v0 = (float)iacc[im][in][0] * cs + facc[im][in][0] + b0;
            float v1 = (float)iacc[im][in][1] * cs + facc[im][in][1] + b1;
            float v2 = (float)iacc[im][in][2] * cs + facc[im][in][2] + b0;
            float v3 = (float)iacc[im][in][3] * cs + facc[im][in][3] + b1;
            if (LAYER1) {
                v0 = 0.5f * v0 * (1.0f + erff(v0 * 0.70710678118654752f));
                v1 = 0.5f * v1 * (1.0f + erff(v1 * 0.70710678118654752f));
                v2 = 0.5f * v2 * (1.0f + erff(v2 * 0.70710678118654752f));
                v3 = 0.5f * v3 * (1.0f + erff(v3 * 0.70710678118654752f));
                lmax = fmaxf(lmax, fmaxf(fmaxf(fabsf(v0), fabsf(v1)),
                                         fmaxf(fabsf(v2), fabsf(v3))));
            }
            float2 w0 = {v0, v1}, w1 = {v2, v3};
            *(float2*)&Out[(size_t)mrow * NCOLS + n0 + ncol] = w0;
            *(float2*)&Out[(size_t)(mrow + 8) * NCOLS + n0 + ncol] = w1;
        }
    }
    if (LAYER1) {
        #pragma unroll
        for (int o = 16; o; o >>= 1) lmax = fmaxf(lmax, __shfl_xor_sync(0xffffffffu, lmax, o));
        if (lane == 0) atomicMax((unsigned int*)amOut, __float_as_uint(lmax));
    }
}

// ============================ launch ======================================
extern "C" void kernel_launch(void* const* d_in, const int* in_sizes, int n_in,
                              void* d_out, int out_size) {
    (void)in_sizes; (void)n_in; (void)out_size;
    const float* x      = (const float*)d_in[0];
    const float* W_fc   = (const float*)d_in[1];
    const float* b_fc   = (const float*)d_in[2];
    const float* A_fc   = (const float*)d_in[3];
    const float* B_fc   = (const float*)d_in[4];
    const float* W_proj = (const float*)d_in[5];
    const float* b_proj = (const float*)d_in[6];
    const float* A_proj = (const float*)d_in[7];
    const float* B_proj = (const float*)d_in[8];
    float* out = (float*)d_out;

    void* p;
    cudaGetSymbolAddress(&p, g_qx);     int8_t* qx            = (int8_t*)p;
    cudaGetSymbolAddress(&p, g_qw1t);   int8_t* qw1t          = (int8_t*)p;
    cudaGetSymbolAddress(&p, g_h);      float* h              = (float*)p;
    cudaGetSymbolAddress(&p, g_qh);     int8_t* qh            = (int8_t*)p;
    cudaGetSymbolAddress(&p, g_qw2t);   int8_t* qw2t          = (int8_t*)p;
    cudaGetSymbolAddress(&p, g_qxe);    __nv_bfloat16* qxe    = (__nv_bfloat16*)p;
    cudaGetSymbolAddress(&p, g_qw1e);   __nv_bfloat16* qw1e   = (__nv_bfloat16*)p;
    cudaGetSymbolAddress(&p, g_qhe);    __nv_bfloat16* qhe    = (__nv_bfloat16*)p;
    cudaGetSymbolAddress(&p, g_qw2e);   __nv_bfloat16* qw2e   = (__nv_bfloat16*)p;
    cudaGetSymbolAddress(&p, g_part);   float* part           = (float*)p;
    cudaGetSymbolAddress(&p, g_absmax); float* am             = (float*)p;

    cudaFuncSetAttribute(gemm_i8<D_IN, D_FF, true>,
                         cudaFuncAttributeMaxDynamicSharedMemorySize, SMEM_GEMM);
    cudaFuncSetAttribute(gemm_i8<D_FF, D_IN, false>,
                         cudaFuncAttributeMaxDynamicSharedMemorySize, SMEM_GEMM);

    // 1) reset absmax scratch (graph-replay determinism)
    init_kernel<<<1, 32>>>(am);
    // 2) absmax of x, W_fc, W_proj in parallel
    absmax3_kernel<<<2560, 256>>>((const float4*)x, (const float4*)W_fc,
                                  (const float4*)W_proj, am);
    // 3) fused quant(x) + LoRA partials x@A_fc
    quantRowA_kernel<<<dim3(M_TOK / 64, D_IN / 1024), 128>>>(x, A_fc, qx, part, D_IN, am + 0);
    // 4) transpose+quantize both weights
    tqBoth_kernel<<<32768, dim3(32, 8)>>>(W_fc, qw1t, W_proj, qw2t, am);
    // 5) reduce xA -> qxe ; extB for both layers
    ext_all_kernel<<<(M_TOK * 16 + D_FF * 16 + D_IN * 16) / 256, 256>>>(
        part, B_fc, B_proj, qxe, qw1e, qw2e);
    // 6) GEMM1 (int8 + bf16 lora ext) + bias + GELU -> h, fused absmax(h)
    gemm_i8<D_IN, D_FF, true><<<(M_TOK / 128) * (D_FF / 128), 256, SMEM_GEMM>>>(
        qx, qw1t, qxe, qw1e, b_fc, am + 0, am + 1, h, am + 3);
    // 7) fused quant(h) + LoRA partials h@A_proj
    quantRowA_kernel<<<dim3(M_TOK / 64, D_FF / 1024), 128>>>(h, A_proj, qh, part, D_FF, am + 3);
    // 8) reduce hA -> qhe
    reduceExtA_kernel<<<(M_TOK * 16) / 256, 256>>>(part, qhe);
    // 9) GEMM2 + bias -> out
    gemm_i8<D_FF, D_IN, false><<<(M_TOK / 128) * (D_IN / 128), 256, SMEM_GEMM>>>(
        qh, qw2t, qhe, qw2e, b_proj, am + 3, am + 2, out, nullptr);
}

// round 7
// speedup vs baseline: 1.4370x; 1.0365x over previous
#include <cuda_runtime.h>
#include <cuda_bf16.h>
#include <cstdint>
#include <cstddef>

// ============================ problem constants ============================
#define M_TOK 4096
#define D_IN  2048
#define D_FF  8192
#define R_LORA 16
#define LORA_SCALE 2.0f

// ============================ device scratch ===============================
__device__ __align__(256) int8_t g_qx  [(size_t)M_TOK * D_IN];
__device__ __align__(256) int8_t g_qw1t[(size_t)D_FF  * D_IN];   // [N][K]
__device__ __align__(256) float  g_h   [(size_t)M_TOK * D_FF];
__device__ __align__(256) int8_t g_qh  [(size_t)M_TOK * D_FF];
__device__ __align__(256) int8_t g_qw2t[(size_t)D_IN  * D_FF];   // [N][K]
__device__ __align__(256) __nv_bfloat16 g_qxe [(size_t)M_TOK * 64];
__device__ __align__(256) __nv_bfloat16 g_qw1e[(size_t)D_FF  * 64];
__device__ __align__(256) __nv_bfloat16 g_qhe [(size_t)M_TOK * 64];
__device__ __align__(256) __nv_bfloat16 g_qw2e[(size_t)D_IN  * 64];
__device__ float g_part[16 * M_TOK * R_LORA];
__device__ float g_absmax[4];   // [0]=x, [1]=W_fc, [2]=W_proj, [3]=h

// ============================ PTX helpers ==================================
__device__ __forceinline__ uint32_t smem_u32(const void* p) {
    uint32_t a;
    asm("{ .reg .u64 t; cvta.to.shared.u64 t, %1; cvt.u32.u64 %0, t; }" : "=r"(a) : "l"(p));
    return a;
}
__device__ __forceinline__ void cp_async16(uint32_t saddr, const void* gptr) {
    asm volatile("cp.async.cg.shared.global [%0], [%1], 16;" :: "r"(saddr), "l"(gptr));
}
#define CP_ASYNC_COMMIT() asm volatile("cp.async.commit_group;" ::: "memory")
#define CP_ASYNC_WAIT2()  asm volatile("cp.async.wait_group 2;" ::: "memory")
#define CP_ASYNC_WAIT3()  asm volatile("cp.async.wait_group 3;" ::: "memory")

__device__ __forceinline__ void ldm_x4(uint32_t* r, uint32_t addr) {
    asm volatile("ldmatrix.sync.aligned.m8n8.x4.shared.b16 {%0,%1,%2,%3}, [%4];"
                 : "=r"(r[0]), "=r"(r[1]), "=r"(r[2]), "=r"(r[3]) : "r"(addr));
}
__device__ __forceinline__ void mma16816(float* c, const uint32_t* a, uint32_t b0, uint32_t b1) {
    asm volatile("mma.sync.aligned.m16n8k16.row.col.f32.bf16.bf16.f32 "
                 "{%0,%1,%2,%3}, {%4,%5,%6,%7}, {%8,%9}, {%0,%1,%2,%3};"
                 : "+f"(c[0]), "+f"(c[1]), "+f"(c[2]), "+f"(c[3])
                 : "r"(a[0]), "r"(a[1]), "r"(a[2]), "r"(a[3]), "r"(b0), "r"(b1));
}
__device__ __forceinline__ void mma16832(int* c, const uint32_t* a, uint32_t b0, uint32_t b1) {
    asm volatile("mma.sync.aligned.m16n8k32.row.col.s32.s8.s8.s32 "
                 "{%0,%1,%2,%3}, {%4,%5,%6,%7}, {%8,%9}, {%0,%1,%2,%3};"
                 : "+r"(c[0]), "+r"(c[1]), "+r"(c[2]), "+r"(c[3])
                 : "r"(a[0]), "r"(a[1]), "r"(a[2]), "r"(a[3]), "r"(b0), "r"(b1));
}

// ============================ small kernels ================================
__global__ void init_kernel(float* am) {
    if (threadIdx.x < 4) am[threadIdx.x] = 0.0f;
}

// one kernel, three tensors in parallel
__global__ void absmax3_kernel(const float4* __restrict__ x, const float4* __restrict__ w1,
                               const float4* __restrict__ w2, float* __restrict__ am) {
    const int NX4 = M_TOK * D_IN / 4, NW4 = D_IN * D_FF / 4;
    const float4* src; int n4, nb, bl; float* out;
    int b = blockIdx.x;
    if (b < 512)       { src = x;  n4 = NX4; out = am;     bl = b;        nb = 512;  }
    else if (b < 1536) { src = w1; n4 = NW4; out = am + 1; bl = b - 512;  nb = 1024; }
    else               { src = w2; n4 = NW4; out = am + 2; bl = b - 1536; nb = 1024; }
    float m = 0.0f;
    for (int i = bl * blockDim.x + threadIdx.x; i < n4; i += nb * blockDim.x) {
        float4 v = src[i];
        m = fmaxf(m, fmaxf(fmaxf(fabsf(v.x), fabsf(v.y)), fmaxf(fabsf(v.z), fabsf(v.w))));
    }
    #pragma unroll
    for (int o = 16; o; o >>= 1) m = fmaxf(m, __shfl_xor_sync(0xffffffffu, m, o));
    __shared__ float s[8];
    if ((threadIdx.x & 31) == 0) s[threadIdx.x >> 5] = m;
    __syncthreads();
    if (threadIdx.x < 32) {
        float v = (threadIdx.x < 8) ? s[threadIdx.x] : 0.0f;
        #pragma unroll
        for (int o = 4; o; o >>= 1) v = fmaxf(v, __shfl_xor_sync(0xffffffffu, v, o));
        if (threadIdx.x == 0) atomicMax((unsigned int*)out, __float_as_uint(v));
    }
}

__device__ __forceinline__ uint32_t pack4(float4 v, float inv) {
    int q0 = (int)fminf(fmaxf(rintf(v.x * inv), -127.f), 127.f);
    int q1 = (int)fminf(fmaxf(rintf(v.y * inv), -127.f), 127.f);
    int q2 = (int)fminf(fmaxf(rintf(v.z * inv), -127.f), 127.f);
    int q3 = (int)fminf(fmaxf(rintf(v.w * inv), -127.f), 127.f);
    return (uint32_t)(q0 & 255) | ((uint32_t)(q1 & 255) << 8) |
           ((uint32_t)(q2 & 255) << 16) | ((uint32_t)(q3 & 255) << 24);
}

// Fused: LoRA-A partials (X @ A16 per k-segment) + int8 quantization of X.
// grid (M/64, K/1024), 128 threads. part split index sp = by*2 + (t&1).
__global__ void __launch_bounds__(128)
quantRowA_kernel(const float* __restrict__ X, const float* __restrict__ A16,
                 int8_t* __restrict__ Q, float* __restrict__ part,
                 int K, const float* __restrict__ am) {
    int t = threadIdx.x;
    int m = blockIdx.x * 64 + (t >> 1);
    int rh = t & 1;
    int kbeg = blockIdx.y * 1024 + rh * 512;
    float acc[16];
    #pragma unroll
    for (int j = 0; j < 16; j++) acc[j] = 0.0f;
    const float4* x4 = (const float4*)(X + (size_t)m * K + kbeg);
    for (int d4 = 0; d4 < 128; d4++) {
        float4 v = x4[d4];
        float xs[4] = {v.x, v.y, v.z, v.w};
        int d = kbeg + d4 * 4;
        #pragma unroll
        for (int j = 0; j < 4; j++) {
            const float4* ap = (const float4*)(A16 + (size_t)(d + j) * 16);
            float4 a0 = ap[0], a1 = ap[1], a2 = ap[2], a3 = ap[3];
            acc[0]  += xs[j] * a0.x; acc[1]  += xs[j] * a0.y;
            acc[2]  += xs[j] * a0.z; acc[3]  += xs[j] * a0.w;
            acc[4]  += xs[j] * a1.x; acc[5]  += xs[j] * a1.y;
            acc[6]  += xs[j] * a1.z; acc[7]  += xs[j] * a1.w;
            acc[8]  += xs[j] * a2.x; acc[9]  += xs[j] * a2.y;
            acc[10] += xs[j] * a2.z; acc[11] += xs[j] * a2.w;
            acc[12] += xs[j] * a3.x; acc[13] += xs[j] * a3.y;
            acc[14] += xs[j] * a3.z; acc[15] += xs[j] * a3.w;
        }
    }
    int sp = blockIdx.y * 2 + rh;
    float* o = part + ((size_t)sp * M_TOK + m) * 16;
    #pragma unroll
    for (int j = 0; j < 16; j++) o[j] = acc[j];
    // phase 2: int8 quantize this block's 64x1024 region (re-read, L2-hot)
    float inv = __fdiv_rn(127.0f, fmaxf(am[0], 1e-8f));
    for (int i = t; i < 4096; i += 128) {
        int row = blockIdx.x * 64 + (i >> 6);
        int col = blockIdx.y * 1024 + (i & 63) * 16;
        const float4* src = (const float4*)(X + (size_t)row * K + col);
        float4 v0 = src[0], v1 = src[1], v2 = src[2], v3 = src[3];
        uint4 w = { pack4(v0, inv), pack4(v1, inv), pack4(v2, inv), pack4(v3, inv) };
        *(uint4*)(Q + (size_t)row * K + col) = w;
    }
}

// Transpose + quantize both weights: W [K,N] fp32 -> Wt [N][K] int8.
// Tile 128(k) x 32(n). Phase 1: coalesced reads, quantize during load, byte-store
// into transposed int8 smem tile (pitch 132B -> conflict-free). Phase 2: each
// thread emits 16B; 8 threads = one contiguous 128B output row. Fully coalesced.
__global__ void __launch_bounds__(256)
tqBoth_kernel(const float* __restrict__ W1, int8_t* __restrict__ Wt1,
              const float* __restrict__ W2, int8_t* __restrict__ Wt2,
              const float* __restrict__ am) {
    __shared__ int8_t tile8[32][132];
    const float* W; int8_t* Wt; int K, N; float inv;
    int bid = blockIdx.x, bx, by;
    if (bid < 4096) { W = W1; Wt = Wt1; K = D_IN; N = D_FF;
                      bx = bid & 255; by = bid >> 8;
                      inv = __fdiv_rn(127.0f, fmaxf(am[1], 1e-8f)); }
    else            { int i = bid - 4096; W = W2; Wt = Wt2; K = D_FF; N = D_IN;
                      bx = i & 63; by = i >> 6;
                      inv = __fdiv_rn(127.0f, fmaxf(am[2], 1e-8f)); }
    int n0 = bx * 32, k0 = by * 128;
    int tx = threadIdx.x & 31, ty = threadIdx.x >> 5;
    for (int r = ty; r < 128; r += 8) {
        float v = W[(size_t)(k0 + r) * N + n0 + tx];
        float q = fminf(fmaxf(rintf(v * inv), -127.f), 127.f);
        tile8[tx][r] = (int8_t)(int)q;
    }
    __syncthreads();
    int j = threadIdx.x >> 3, c0 = (threadIdx.x & 7) * 16;
    uint32_t w[4];
    #pragma unroll
    for (int q = 0; q < 4; q++) {
        uint32_t b0 = (uint8_t)tile8[j][c0 + q * 4 + 0];
        uint32_t b1 = (uint8_t)tile8[j][c0 + q * 4 + 1];
        uint32_t b2 = (uint8_t)tile8[j][c0 + q * 4 + 2];
        uint32_t b3 = (uint8_t)tile8[j][c0 + q * 4 + 3];
        w[q] = b0 | (b1 << 8) | (b2 << 16) | (b3 << 24);
    }
    *(uint4*)(Wt + (size_t)(n0 + j) * K + k0 + c0) = *(uint4*)w;
}

__device__ __forceinline__ void write_extA(__nv_bfloat16* row, int r, float a) {
    __nv_bfloat16 hi = __float2bfloat16_rn(a);
    __nv_bfloat16 lo = __float2bfloat16_rn(a - __bfloat162float(hi));
    row[r] = hi; row[16 + r] = hi; row[32 + r] = lo; row[48 + r] = __float2bfloat16_rn(0.f);
}
__device__ __forceinline__ void write_extB(__nv_bfloat16* row, int r, float b) {
    __nv_bfloat16 hi = __float2bfloat16_rn(b);
    __nv_bfloat16 lo = __float2bfloat16_rn(b - __bfloat162float(hi));
    row[r] = hi; row[16 + r] = lo; row[32 + r] = hi; row[48 + r] = __float2bfloat16_rn(0.f);
}

// reduce part(4 splits) -> qxe ; extB for both layers
__global__ void ext_all_kernel(const float* __restrict__ part,
                               const float* __restrict__ B_fc, const float* __restrict__ B_proj,
                               __nv_bfloat16* __restrict__ qxe,
                               __nv_bfloat16* __restrict__ qw1e,
                               __nv_bfloat16* __restrict__ qw2e) {
    int gid = blockIdx.x * 256 + threadIdx.x;
    if (gid < M_TOK * 16) {
        int m = gid >> 4, r = gid & 15;
        float s = 0.0f;
        for (int sp = 0; sp < 4; sp++) s += part[((size_t)sp * M_TOK + m) * 16 + r];
        write_extA(qxe + (size_t)m * 64, r, s * LORA_SCALE);
    } else if (gid < M_TOK * 16 + D_FF * 16) {
        int i = gid - M_TOK * 16; int n = i >> 4, r = i & 15;
        write_extB(qw1e + (size_t)n * 64, r, B_fc[(size_t)r * D_FF + n]);
    } else if (gid < M_TOK * 16 + D_FF * 16 + D_IN * 16) {
        int i = gid - M_TOK * 16 - D_FF * 16; int n = i >> 4, r = i & 15;
        write_extB(qw2e + (size_t)n * 64, r, B_proj[(size_t)r * D_IN + n]);
    }
}

// reduce part(16 splits) -> qhe
__global__ void reduceExtA_kernel(const float* __restrict__ part, __nv_bfloat16* __restrict__ qhe) {
    int gid = blockIdx.x * 256 + threadIdx.x;
    if (gid < M_TOK * 16) {
        int m = gid >> 4, r = gid & 15;
        float s = 0.0f;
        for (int sp = 0; sp < 16; sp++) s += part[((size_t)sp * M_TOK + m) * 16 + r];
        write_extA(qhe + (size_t)m * 64, r, s * LORA_SCALE);
    }
}

// ============================ int8 mma GEMM ================================
// CTA 128x128, k-chunk 128 int8, 4-stage cp.async pipeline (depth-3 prefetch),
// 8 warps (2m x 4n), warp 64x32. LoRA ext pass runs FIRST out of stage 3.
static constexpr int STAGE_BYTES = 32768;              // A 16KB + B 16KB
static constexpr int BIAS_OFF    = 4 * STAGE_BYTES;
static constexpr int SMEM_GEMM   = BIAS_OFF + 640;

__device__ __forceinline__ void load_tile8(uint32_t sbase, const int8_t* __restrict__ src,
                                           int row0, int k0, int ldk) {
    int tid = threadIdx.x;
    #pragma unroll
    for (int i = 0; i < 4; i++) {
        int idx = i * 256 + tid;
        int r   = idx >> 3;
        int ch  = idx & 7;
        uint32_t dst = sbase + r * 128 + ((ch ^ (r & 7)) << 4);
        cp_async16(dst, src + (size_t)(row0 + r) * ldk + k0 + ch * 16);
    }
}
__device__ __forceinline__ void load_tile16(uint32_t sbase, const __nv_bfloat16* __restrict__ src,
                                            int row0, int ldk) {
    int tid = threadIdx.x;
    #pragma unroll
    for (int i = 0; i < 4; i++) {
        int idx = i * 256 + tid;
        int r   = idx >> 3;
        int ch  = idx & 7;
        uint32_t dst = sbase + r * 128 + ((ch ^ (r & 7)) << 4);
        cp_async16(dst, src + (size_t)(row0 + r) * ldk + ch * 8);
    }
}

template <int KTOT, int NCOLS, bool LAYER1>
__global__ void __launch_bounds__(256, 1)
gemm_i8(const int8_t* __restrict__ Aq, const int8_t* __restrict__ Bq,
        const __nv_bfloat16* __restrict__ Ae, const __nv_bfloat16* __restrict__ Be,
        const float* __restrict__ bias, const float* __restrict__ amA,
        const float* __restrict__ amB, float* __restrict__ Out, float* __restrict__ amOut) {
    extern __shared__ char smem[];
    uint32_t sb = smem_u32(smem);
    int tid = threadIdx.x, wid = tid >> 5, lane = tid & 31;
    constexpr int NT = NCOLS / 128;
    int mt = blockIdx.x / NT, nt = blockIdx.x % NT;
    int m0 = mt * 128, n0 = nt * 128;
    int m0w = (wid >> 2) * 64;
    int n0w = (wid & 3) * 32;

    float* bs = (float*)(smem + BIAS_OFF);
    if (tid < 128) bs[tid] = bias[n0 + tid];

    // prefetch: ext -> stage3 (g0), kc0..2 -> stages 0..2 (g1..g3)
    load_tile16(sb + 3 * STAGE_BYTES, Ae, m0, 64);
    load_tile16(sb + 3 * STAGE_BYTES + 16384, Be, n0, 64);
    CP_ASYNC_COMMIT();
    constexpr int NKC = KTOT / 128;
    load_tile8(sb, Aq, m0, 0, KTOT);
    load_tile8(sb + 16384, Bq, n0, 0, KTOT);
    CP_ASYNC_COMMIT();
    load_tile8(sb + STAGE_BYTES, Aq, m0, 128, KTOT);
    load_tile8(sb + STAGE_BYTES + 16384, Bq, n0, 128, KTOT);
    CP_ASYNC_COMMIT();
    load_tile8(sb + 2 * STAGE_BYTES, Aq, m0, 256, KTOT);
    load_tile8(sb + 2 * STAGE_BYTES + 16384, Bq, n0, 256, KTOT);
    CP_ASYNC_COMMIT();

    // ldmatrix per-lane addressing
    int rA = lane & 15, selA = lane >> 4;
    int rB = ((lane >> 4) << 3) | (lane & 7);
    int selB = (lane >> 3) & 1;
    uint32_t rowA = (uint32_t)(m0w + rA) * 128;
    uint32_t rowB = (uint32_t)(n0w + rB) * 128;
    uint32_t swA = (uint32_t)(rA & 7), swB = (uint32_t)(rB & 7);

    // LoRA ext pass first (stage 3): bf16, 3 k16 steps (cols 48-63 zero)
    float facc[4][4][4];
    #pragma unroll
    for (int a = 0; a < 4; a++)
        #pragma unroll
        for (int b = 0; b < 4; b++)
            #pragma unroll
            for (int c = 0; c < 4; c++) facc[a][b][c] = 0.0f;
    CP_ASYNC_WAIT3();
    __syncthreads();
    {
        uint32_t eA = sb + 3 * STAGE_BYTES, eB = eA + 16384;
        #pragma unroll
        for (int kq = 0; kq < 3; kq++) {
            uint32_t afr[4][4], bfr[2][4];
            uint32_t chA = (((uint32_t)(2 * kq + selA) ^ swA) << 4);
            uint32_t chB = (((uint32_t)(2 * kq + selB) ^ swB) << 4);
            #pragma unroll
            for (int im = 0; im < 4; im++)
                ldm_x4(afr[im], eA + rowA + im * 16 * 128 + chA);
            #pragma unroll
            for (int p = 0; p < 2; p++)
                ldm_x4(bfr[p], eB + rowB + p * 16 * 128 + chB);
            #pragma unroll
            for (int im = 0; im < 4; im++)
                #pragma unroll
                for (int in = 0; in < 4; in++)
                    mma16816(facc[im][in], afr[im], bfr[in >> 1][(in & 1) * 2],
                             bfr[in >> 1][(in & 1) * 2 + 1]);
        }
    }

    int iacc[4][4][4];
    #pragma unroll
    for (int a = 0; a < 4; a++)
        #pragma unroll
        for (int b = 0; b < 4; b++)
            #pragma unroll
            for (int c = 0; c < 4; c++) iacc[a][b][c] = 0;

    for (int kc = 0; kc < NKC; kc++) {
        CP_ASYNC_WAIT2();
        __syncthreads();
        if (kc + 3 < NKC) {
            int st = (kc + 3) & 3;
            load_tile8(sb + st * STAGE_BYTES, Aq, m0, (kc + 3) * 128, KTOT);
            load_tile8(sb + st * STAGE_BYTES + 16384, Bq, n0, (kc + 3) * 128, KTOT);
        }
        CP_ASYNC_COMMIT();
        uint32_t bA = sb + (kc & 3) * STAGE_BYTES;
        uint32_t bB = bA + 16384;
        #pragma unroll
        for (int kq = 0; kq < 4; kq++) {
            uint32_t afr[4][4], bfr[2][4];
            uint32_t chA = (((uint32_t)(2 * kq + selA) ^ swA) << 4);
            uint32_t chB = (((uint32_t)(2 * kq + selB) ^ swB) << 4);
            #pragma unroll
            for (int im = 0; im < 4; im++)
                ldm_x4(afr[im], bA + rowA + im * 16 * 128 + chA);
            #pragma unroll
            for (int p = 0; p < 2; p++)
                ldm_x4(bfr[p], bB + rowB + p * 16 * 128 + chB);
            #pragma unroll
            for (int im = 0; im < 4; im++)
                #pragma unroll
                for (int in = 0; in < 4; in++)
                    mma16832(iacc[im][in], afr[im], bfr[in >> 1][(in & 1) * 2],
                             bfr[in >> 1][(in & 1) * 2 + 1]);
        }
    }

    float cs = __fdiv_rn(fmaxf(amA[0], 1e-8f), 127.0f) *
               __fdiv_rn(fmaxf(amB[0], 1e-8f), 127.0f);
    float lmax = 0.0f;
    #pragma unroll
    for (int im = 0; im < 4; im++) {
        int mrow = m0 + m0w + im * 16 + (lane >> 2);
        #pragma unroll
        for (int in = 0; in < 4; in++) {
            int ncol = n0w + in * 8 + 2 * (lane & 3);
            float b0 = bs[ncol], b1 = bs[ncol + 1];
            float v0 = (float)iacc[im][in][0] * cs + facc[im][in][0] + b0;
            float v1 = (float)iacc[im][in][1] * cs + facc[im][in][1] + b1;
            float v2 = (float)iacc[im][in][2] * cs + facc[im][in][2] + b0;
            float v3 = (float)iacc[im][in][3] * cs + facc[im][in][3] + b1;
            if (LAYER1) {
                v0 = 0.5f * v0 * (1.0f + erff(v0 * 0.70710678118654752f));
                v1 = 0.5f * v1 * (1.0f + erff(v1 * 0.70710678118654752f));
                v2 = 0.5f * v2 * (1.0f + erff(v2 * 0.70710678118654752f));
                v3 = 0.5f * v3 * (1.0f + erff(v3 * 0.70710678118654752f));
                lmax = fmaxf(lmax, fmaxf(fmaxf(fabsf(v0), fabsf(v1)),
                                         fmaxf(fabsf(v2), fabsf(v3))));
            }
            float2 w0 = {v0, v1}, w1 = {v2, v3};
            *(float2*)&Out[(size_t)mrow * NCOLS + n0 + ncol] = w0;
            *(float2*)&Out[(size_t)(mrow + 8) * NCOLS + n0 + ncol] = w1;
        }
    }
    if (LAYER1) {
        #pragma unroll
        for (int o = 16; o; o >>= 1) lmax = fmaxf(lmax, __shfl_xor_sync(0xffffffffu, lmax, o));
        if (lane == 0) atomicMax((unsigned int*)amOut, __float_as_uint(lmax));
    }
}

// ============================ launch ======================================
extern "C" void kernel_launch(void* const* d_in, const int* in_sizes, int n_in,
                              void* d_out, int out_size) {
    (void)in_sizes; (void)n_in; (void)out_size;
    const float* x      = (const float*)d_in[0];
    const float* W_fc   = (const float*)d_in[1];
    const float* b_fc   = (const float*)d_in[2];
    const float* A_fc   = (const float*)d_in[3];
    const float* B_fc   = (const float*)d_in[4];
    const float* W_proj = (const float*)d_in[5];
    const float* b_proj = (const float*)d_in[6];
    const float* A_proj = (const float*)d_in[7];
    const float* B_proj = (const float*)d_in[8];
    float* out = (float*)d_out;

    void* p;
    cudaGetSymbolAddress(&p, g_qx);     int8_t* qx            = (int8_t*)p;
    cudaGetSymbolAddress(&p, g_qw1t);   int8_t* qw1t          = (int8_t*)p;
    cudaGetSymbolAddress(&p, g_h);      float* h              = (float*)p;
    cudaGetSymbolAddress(&p, g_qh);     int8_t* qh            = (int8_t*)p;
    cudaGetSymbolAddress(&p, g_qw2t);   int8_t* qw2t          = (int8_t*)p;
    cudaGetSymbolAddress(&p, g_qxe);    __nv_bfloat16* qxe    = (__nv_bfloat16*)p;
    cudaGetSymbolAddress(&p, g_qw1e);   __nv_bfloat16* qw1e   = (__nv_bfloat16*)p;
    cudaGetSymbolAddress(&p, g_qhe);    __nv_bfloat16* qhe    = (__nv_bfloat16*)p;
    cudaGetSymbolAddress(&p, g_qw2e);   __nv_bfloat16* qw2e   = (__nv_bfloat16*)p;
    cudaGetSymbolAddress(&p, g_part);   float* part           = (float*)p;
    cudaGetSymbolAddress(&p, g_absmax); float* am             = (float*)p;

    cudaFuncSetAttribute(gemm_i8<D_IN, D_FF, true>,
                         cudaFuncAttributeMaxDynamicSharedMemorySize, SMEM_GEMM);
    cudaFuncSetAttribute(gemm_i8<D_FF, D_IN, false>,
                         cudaFuncAttributeMaxDynamicSharedMemorySize, SMEM_GEMM);

    // 1) reset absmax scratch (graph-replay determinism)
    init_kernel<<<1, 32>>>(am);
    // 2) absmax of x, W_fc, W_proj in parallel
    absmax3_kernel<<<2560, 256>>>((const float4*)x, (const float4*)W_fc,
                                  (const float4*)W_proj, am);
    // 3) fused quant(x) + LoRA partials x@A_fc
    quantRowA_kernel<<<dim3(M_TOK / 64, D_IN / 1024), 128>>>(x, A_fc, qx, part, D_IN, am + 0);
    // 4) transpose+quantize both weights (coalesced 128B writes)
    tqBoth_kernel<<<8192, 256>>>(W_fc, qw1t, W_proj, qw2t, am);
    // 5) reduce xA -> qxe ; extB for both layers
    ext_all_kernel<<<(M_TOK * 16 + D_FF * 16 + D_IN * 16) / 256, 256>>>(
        part, B_fc, B_proj, qxe, qw1e, qw2e);
    // 6) GEMM1 (int8 + bf16 lora ext) + bias + GELU -> h, fused absmax(h)
    gemm_i8<D_IN, D_FF, true><<<(M_TOK / 128) * (D_FF / 128), 256, SMEM_GEMM>>>(
        qx, qw1t, qxe, qw1e, b_fc, am + 0, am + 1, h, am + 3);
    // 7) fused quant(h) + LoRA partials h@A_proj
    quantRowA_kernel<<<dim3(M_TOK / 64, D_FF / 1024), 128>>>(h, A_proj, qh, part, D_FF, am + 3);
    // 8) reduce hA -> qhe
    reduceExtA_kernel<<<(M_TOK * 16) / 256, 256>>>(part, qhe);
    // 9) GEMM2 + bias -> out
    gemm_i8<D_FF, D_IN, false><<<(M_TOK / 128) * (D_IN / 128), 256, SMEM_GEMM>>>(
        qh, qw2t, qhe, qw2e, b_proj, am + 3, am + 2, out, nullptr);
}